// round 6
// baseline (speedup 1.0000x reference)
#include <cuda_runtime.h>
#include <math.h>

#define SEQN 64
#define BSN  32
#define NHID 256
#define G4   1024

#define TK        16                    // k-rows per W tile
#define ND        3                     // ring depth
#define TILEB     (TK * G4 * 4)         // 65536 bytes per tile
#define NT_STEP   (NHID / TK)           // 16 tiles per step
#define NT_TOT    (SEQN * NT_STEP)      // 1024 tiles total
#define CSZ       8                     // cluster size
#define SLICEB    (TILEB / CSZ)         // 8192 bytes per rank slice
#define NTHR      288                   // 8 compute warps + 1 producer warp

__device__ float  g_Gx[BSN * SEQN * G4];
__device__ float4 g_Wt[256 * 256];
__device__ float  g_state_f[BSN * NHID * 64];
__device__ float  g_state_a[BSN * NHID * 64];
__device__ float  g_hxi[BSN * 64 * 64];
__device__ float  g_hx_f[BSN * 64];
__device__ float  g_hx_a[BSN * 64];
__device__ float  g_P_f[BSN * 64 * 64];
__device__ float  g_P_a[BSN * 64 * 64];
__device__ float  g_HA[BSN * 64 * 64];
__device__ float  g_sol[BSN * 64 * 64];
__device__ float  g_part[BSN * 2];

typedef unsigned long long ull;

__device__ __forceinline__ ull pk2(float a, float b) {
    ull r;
    asm("mov.b64 %0, {%1, %2};" : "=l"(r) : "f"(a), "f"(b));
    return r;
}
__device__ __forceinline__ float2 upk2(ull v) {
    float2 r;
    asm("mov.b64 {%0, %1}, %2;" : "=f"(r.x), "=f"(r.y) : "l"(v));
    return r;
}
__device__ __forceinline__ void fma2(ull& acc, ull a, ull b) {
    asm("fma.rn.f32x2 %0, %1, %2, %0;" : "+l"(acc) : "l"(a), "l"(b));
}
__device__ __forceinline__ float sigf(float x) { return 1.0f / (1.0f + __expf(-x)); }

__device__ __forceinline__ unsigned smem_u32(const void* p) {
    unsigned a;
    asm("{ .reg .u64 t; cvta.to.shared.u64 t, %1; cvt.u32.u64 %0, t; }"
        : "=r"(a) : "l"(p));
    return a;
}
__device__ __forceinline__ void mbar_init(unsigned mbar, unsigned cnt) {
    asm volatile("mbarrier.init.shared.b64 [%0], %1;" :: "r"(mbar), "r"(cnt) : "memory");
}
__device__ __forceinline__ void mbar_expect_tx(unsigned mbar, unsigned bytes) {
    asm volatile("mbarrier.arrive.expect_tx.shared.b64 _, [%0], %1;"
                 :: "r"(mbar), "r"(bytes) : "memory");
}
__device__ __forceinline__ void mbar_arrive_local(unsigned mbar) {
    asm volatile("mbarrier.arrive.shared.b64 _, [%0];" :: "r"(mbar) : "memory");
}
__device__ __forceinline__ void mbar_wait(unsigned mbar, unsigned phase) {
    asm volatile(
        "{\n\t"
        ".reg .pred P;\n\t"
        "LW%=:\n\t"
        "mbarrier.try_wait.parity.acquire.cta.shared::cta.b64 P, [%0], %1, 0x989680;\n\t"
        "@P bra LD%=;\n\t"
        "bra LW%=;\n\t"
        "LD%=:\n\t"
        "}"
        :: "r"(mbar), "r"(phase) : "memory");
}
__device__ __forceinline__ void bulk_g2s_mc(unsigned dst, const void* src,
                                            unsigned bytes, unsigned mbar,
                                            unsigned short mask) {
    asm volatile(
        "cp.async.bulk.shared::cluster.global.mbarrier::complete_tx::bytes.multicast::cluster"
        " [%0], [%1], %2, [%3], %4;"
        :: "r"(dst), "l"(src), "r"(bytes), "r"(mbar), "h"(mask) : "memory");
}
__device__ __forceinline__ void mbar_arrive_remote(unsigned mbar, unsigned rank) {
    asm volatile(
        "{ .reg .b32 ra; mapa.shared::cluster.u32 ra, %0, %1;"
        " mbarrier.arrive.shared::cluster.b64 _, [ra]; }"
        :: "r"(mbar), "r"(rank) : "memory");
}
#define CBAR() asm volatile("bar.sync 1, 256;" ::: "memory")   // compute warps only

// ---------- W_hh -> gate-interleaved float4 layout ----------
__global__ void ek_wprep(const float* __restrict__ W) {
    int k = blockIdx.x, j = threadIdx.x;
    g_Wt[k * 256 + j] = make_float4(W[k * G4 + j], W[k * G4 + 256 + j],
                                    W[k * G4 + 512 + j], W[k * G4 + 768 + j]);
}

// ---------- Gx[b*64+t][1024] = x[b][t][:] @ W_ih + b ----------
__global__ void __launch_bounds__(256) ek_gx(const float* __restrict__ x,
                                             const float* __restrict__ Wih,
                                             const float* __restrict__ bias) {
    __shared__ float As[32][65];
    __shared__ float Bs[32][64];
    const int tid = threadIdx.x;
    const int row0 = blockIdx.y * 64, col0 = blockIdx.x * 64;
    const int ty = tid >> 4, tx = tid & 15;
    float acc[4][4] = {};
    for (int kb = 0; kb < 256; kb += 32) {
        #pragma unroll
        for (int l = 0; l < 8; l++) {
            int e = l * 256 + tid, r = e >> 5, k = e & 31;
            As[k][r] = x[(size_t)(row0 + r) * 256 + kb + k];
        }
        #pragma unroll
        for (int l = 0; l < 8; l++) {
            int e = l * 256 + tid, k = e >> 6, c = e & 63;
            Bs[k][c] = Wih[(size_t)(kb + k) * G4 + col0 + c];
        }
        __syncthreads();
        #pragma unroll
        for (int k = 0; k < 32; k++) {
            float av[4], bv[4];
            #pragma unroll
            for (int i = 0; i < 4; i++) av[i] = As[k][ty * 4 + i];
            #pragma unroll
            for (int j = 0; j < 4; j++) bv[j] = Bs[k][tx * 4 + j];
            #pragma unroll
            for (int i = 0; i < 4; i++)
                #pragma unroll
                for (int j = 0; j < 4; j++) acc[i][j] += av[i] * bv[j];
        }
        __syncthreads();
    }
    #pragma unroll
    for (int i = 0; i < 4; i++)
        #pragma unroll
        for (int j = 0; j < 4; j++)
            g_Gx[(size_t)(row0 + ty * 4 + i) * G4 + col0 + tx * 4 + j] =
                acc[i][j] + bias[col0 + tx * 4 + j];
}

// ---------- LSTM recurrence ----------
// 16 clusters of 8 CTAs. W tiles delivered by cooperative-slice TMA multicast.
// Warp specialization: warps 0-7 compute (256 thr), warp 8 runs the full
// release/refill protocol so cluster skew never blocks compute.
__global__ void __launch_bounds__(NTHR, 1) __cluster_dims__(CSZ, 1, 1)
ek_lstm(const float* __restrict__ st0,
        const float* __restrict__ eps_h,
        const float* __restrict__ eps_c,
        const float* __restrict__ qp,
        const float* __restrict__ ep) {
    extern __shared__ char smd[];
    float4*     ws  = (float4*)smd;                           // ND * TK*256 float4
    ulonglong2* hsd = (ulonglong2*)(smd + ND * TILEB);        // [2][256][2]
    ull*        mbf = (ull*)(smd + ND * TILEB + 16384);       // full[ND]
    ull*        mbe = (ull*)(smd + ND * TILEB + 16384 + 64);  // empty[ND] (cluster)
    ull*        mbc = (ull*)(smd + ND * TILEB + 16384 + 128); // cons[ND]  (local)

    const int jt = threadIdx.x;
    const int b  = blockIdx.x >> 2;
    const int m0 = (blockIdx.x & 3) * 8;
    const unsigned fb0 = smem_u32(mbf);
    const unsigned eb0 = smem_u32(mbe);
    const unsigned lc0 = smem_u32(mbc);
    const unsigned ws0 = smem_u32(ws);
    unsigned rank;
    asm("mov.u32 %0, %%cluster_ctarank;" : "=r"(rank));

    if (jt == 0) {
        #pragma unroll
        for (int d = 0; d < ND; d++) {
            mbar_init(fb0 + d * 8, 1);
            mbar_init(eb0 + d * 8, CSZ);
            mbar_init(lc0 + d * 8, 1);
        }
    }
    __syncthreads();
    asm volatile("barrier.cluster.arrive.aligned;" ::: "memory");
    asm volatile("barrier.cluster.wait.aligned;" ::: "memory");

    if (jt >= 256) {
        // ---------------- producer warp ----------------
        if (jt == 256) {
            #pragma unroll
            for (int d = 0; d < ND; d++) {
                mbar_expect_tx(fb0 + d * 8, TILEB);
                bulk_g2s_mc(ws0 + d * TILEB + rank * SLICEB,
                            (const char*)g_Wt + (size_t)d * TILEB + rank * SLICEB,
                            SLICEB, fb0 + d * 8, (unsigned short)0xFF);
            }
            for (unsigned g = 0; g + ND < NT_TOT; g++) {
                const unsigned s  = g % ND;
                const unsigned ph = (g / ND) & 1;
                mbar_wait(lc0 + s * 8, ph);          // my CTA consumed gen g
                #pragma unroll
                for (unsigned rr = 0; rr < CSZ; rr++)
                    mbar_arrive_remote(eb0 + s * 8, rr);
                mbar_wait(eb0 + s * 8, ph);          // all 8 CTAs consumed gen g
                unsigned src_tile = (g + ND) % NT_STEP;
                mbar_expect_tx(fb0 + s * 8, TILEB);
                bulk_g2s_mc(ws0 + s * TILEB + rank * SLICEB,
                            (const char*)g_Wt + (size_t)src_tile * TILEB + rank * SLICEB,
                            SLICEB, fb0 + s * 8, (unsigned short)0xFF);
            }
        }
    } else {
        // ---------------- compute warps ----------------
        float c[8];
        {
            const float* srow = st0 + ((size_t)b * NHID + jt) * 64;
            float h0[8];
            #pragma unroll
            for (int i = 0; i < 8; i++) { h0[i] = srow[m0 + i]; c[i] = srow[32 + m0 + i]; }
            #pragma unroll
            for (int p = 0; p < 2; p++) {
                ulonglong2 v;
                v.x = pk2(h0[4 * p], h0[4 * p + 1]);
                v.y = pk2(h0[4 * p + 2], h0[4 * p + 3]);
                hsd[(0 * 256 + jt) * 2 + p] = v;
            }
        }
        CBAR();

        unsigned g = 0;
        for (int t = 0; t < SEQN; t++) {
            const int cb = t & 1, nb = cb ^ 1;
            const float* gx = g_Gx + ((size_t)b * SEQN + t) * G4 + jt;
            ull acc[4][4];
            #pragma unroll
            for (int gg = 0; gg < 4; gg++) {
                float gv = gx[gg * 256];
                ull gp = pk2(gv, gv);
                #pragma unroll
                for (int p = 0; p < 4; p++) acc[p][gg] = gp;
            }
            for (int tile = 0; tile < NT_STEP; tile++, g++) {
                const unsigned s  = g % ND;
                const unsigned ph = (g / ND) & 1;
                mbar_wait(fb0 + s * 8, ph);
                const float4* wt = ws + (size_t)s * (TK * 256) + jt;
                const ulonglong2* hp = hsd + ((size_t)cb * 256 + tile * TK) * 2;
                #pragma unroll
                for (int kk = 0; kk < TK; kk++) {
                    float4 w = wt[kk * 256];
                    ulonglong2 h01 = hp[kk * 2 + 0];
                    ulonglong2 h23 = hp[kk * 2 + 1];
                    ull wp0 = pk2(w.x, w.x), wp1 = pk2(w.y, w.y);
                    ull wp2 = pk2(w.z, w.z), wp3 = pk2(w.w, w.w);
                    fma2(acc[0][0], h01.x, wp0); fma2(acc[0][1], h01.x, wp1);
                    fma2(acc[0][2], h01.x, wp2); fma2(acc[0][3], h01.x, wp3);
                    fma2(acc[1][0], h01.y, wp0); fma2(acc[1][1], h01.y, wp1);
                    fma2(acc[1][2], h01.y, wp2); fma2(acc[1][3], h01.y, wp3);
                    fma2(acc[2][0], h23.x, wp0); fma2(acc[2][1], h23.x, wp1);
                    fma2(acc[2][2], h23.x, wp2); fma2(acc[2][3], h23.x, wp3);
                    fma2(acc[3][0], h23.y, wp0); fma2(acc[3][1], h23.y, wp1);
                    fma2(acc[3][2], h23.y, wp2); fma2(acc[3][3], h23.y, wp3);
                }
                CBAR();                      // all compute threads done with slot s
                if (jt == 0) mbar_arrive_local(lc0 + s * 8);   // hand to producer
            }
            {
                ulonglong2 v0, v1;
                {
                    float2 gi = upk2(acc[0][0]), gf = upk2(acc[0][1]);
                    float2 gg2 = upk2(acc[0][2]), go = upk2(acc[0][3]);
                    float c0 = sigf(gf.x) * c[0] + sigf(gi.x) * tanhf(gg2.x);
                    float c1 = sigf(gf.y) * c[1] + sigf(gi.y) * tanhf(gg2.y);
                    c[0] = c0; c[1] = c1;
                    v0.x = pk2(sigf(go.x) * tanhf(c0), sigf(go.y) * tanhf(c1));
                }
                {
                    float2 gi = upk2(acc[1][0]), gf = upk2(acc[1][1]);
                    float2 gg2 = upk2(acc[1][2]), go = upk2(acc[1][3]);
                    float c0 = sigf(gf.x) * c[2] + sigf(gi.x) * tanhf(gg2.x);
                    float c1 = sigf(gf.y) * c[3] + sigf(gi.y) * tanhf(gg2.y);
                    c[2] = c0; c[3] = c1;
                    v0.y = pk2(sigf(go.x) * tanhf(c0), sigf(go.y) * tanhf(c1));
                }
                {
                    float2 gi = upk2(acc[2][0]), gf = upk2(acc[2][1]);
                    float2 gg2 = upk2(acc[2][2]), go = upk2(acc[2][3]);
                    float c0 = sigf(gf.x) * c[4] + sigf(gi.x) * tanhf(gg2.x);
                    float c1 = sigf(gf.y) * c[5] + sigf(gi.y) * tanhf(gg2.y);
                    c[4] = c0; c[5] = c1;
                    v1.x = pk2(sigf(go.x) * tanhf(c0), sigf(go.y) * tanhf(c1));
                }
                {
                    float2 gi = upk2(acc[3][0]), gf = upk2(acc[3][1]);
                    float2 gg2 = upk2(acc[3][2]), go = upk2(acc[3][3]);
                    float c0 = sigf(gf.x) * c[6] + sigf(gi.x) * tanhf(gg2.x);
                    float c1 = sigf(gf.y) * c[7] + sigf(gi.y) * tanhf(gg2.y);
                    c[6] = c0; c[7] = c1;
                    v1.y = pk2(sigf(go.x) * tanhf(c0), sigf(go.y) * tanhf(c1));
                }
                hsd[(nb * 256 + jt) * 2 + 0] = v0;
                hsd[(nb * 256 + jt) * 2 + 1] = v1;
            }
            CBAR();   // new h visible before next step
        }

        const float nq = fabsf(qp[0]), ne = fabsf(ep[0]);
        float* orow = g_state_f + ((size_t)b * NHID + jt) * 64;
        ulonglong2 f0 = hsd[(0 * 256 + jt) * 2 + 0];
        ulonglong2 f1 = hsd[(0 * 256 + jt) * 2 + 1];
        float2 hf[4] = { upk2(f0.x), upk2(f0.y), upk2(f1.x), upk2(f1.y) };
        #pragma unroll
        for (int p = 0; p < 4; p++) {
            int ma = m0 + 2 * p, mb2 = ma + 1;
            orow[ma]  = hf[p].x + nq * eps_h[((size_t)ma * BSN + b) * NHID + jt];
            orow[mb2] = hf[p].y + nq * eps_h[((size_t)mb2 * BSN + b) * NHID + jt];
            orow[32 + ma]  = c[2 * p]     + ne * eps_c[((size_t)ma * BSN + b) * NHID + jt];
            orow[32 + mb2] = c[2 * p + 1] + ne * eps_c[((size_t)mb2 * BSN + b) * NHID + jt];
        }
    }
    // no CTA may exit while peer multicasts targeting its smem are in flight
    asm volatile("barrier.cluster.arrive.aligned;" ::: "memory");
    asm volatile("barrier.cluster.wait.aligned;" ::: "memory");
}

// ---------- hxi[b][m][i] = Wh[m][:] @ state[b][:][i] + bh[m] ----------
__global__ void __launch_bounds__(256) ek_obs(const float* __restrict__ Wh,
                                              const float* __restrict__ bh,
                                              const float* __restrict__ state,
                                              float* __restrict__ hxi) {
    const int b = blockIdx.x, tid = threadIdx.x;
    __shared__ float whs[64 * 64];
    __shared__ float ss[64 * 64];
    const int i = tid & 63, mg = tid >> 6;
    float acc[16] = {};
    for (int nt = 0; nt < NHID; nt += 64) {
        for (int idx = tid; idx < 4096; idx += 256) {
            whs[idx] = Wh[(size_t)(idx >> 6) * NHID + nt + (idx & 63)];
            ss[idx]  = state[(size_t)b * (NHID * 64) + (size_t)(nt + (idx >> 6)) * 64 + (idx & 63)];
        }
        __syncthreads();
        #pragma unroll 4
        for (int n = 0; n < 64; n++) {
            float sv = ss[n * 64 + i];
            #pragma unroll
            for (int mi = 0; mi < 16; mi++)
                acc[mi] += whs[(mg * 16 + mi) * 64 + n] * sv;
        }
        __syncthreads();
    }
    #pragma unroll
    for (int mi = 0; mi < 16; mi++) {
        int m = mg * 16 + mi;
        hxi[((size_t)b * 64 + m) * 64 + i] = acc[mi] + bh[m];
    }
}

// ---------- mean / center / P = cov/63 + r^2 I ----------
__global__ void __launch_bounds__(256) ek_stats(const float* __restrict__ rp,
                                                const float* __restrict__ hxi,
                                                float* __restrict__ hx,
                                                float* __restrict__ P,
                                                int save_ha,
                                                float* __restrict__ out_mu,
                                                float* __restrict__ out_sig) {
    const int b = blockIdx.x, tid = threadIdx.x;
    __shared__ float hsm[64 * 65];
    __shared__ float mean_s[64];
    for (int idx = tid; idx < 4096; idx += 256) {
        int m = idx >> 6, i = idx & 63;
        hsm[m * 65 + i] = hxi[(size_t)b * 4096 + idx];
    }
    __syncthreads();
    if (tid < 64) {
        float s = 0.f;
        for (int i = 0; i < 64; i++) s += hsm[tid * 65 + i];
        s *= (1.0f / 64.0f);
        mean_s[tid] = s;
        hx[b * 64 + tid] = s;
        if (out_mu) out_mu[b * 64 + tid] = s;
    }
    __syncthreads();
    for (int idx = tid; idx < 4096; idx += 256) {
        int m = idx >> 6, i = idx & 63;
        float v = hsm[m * 65 + i] - mean_s[m];
        hsm[m * 65 + i] = v;
        if (save_ha) g_HA[(size_t)b * 4096 + idx] = v;
    }
    __syncthreads();
    const float rr = rp[0] * rp[0];
    const int m2 = tid & 63, mg = tid >> 6;
    for (int mi = 0; mi < 16; mi++) {
        int m = mg * 16 + mi;
        float s = 0.f;
        for (int i = 0; i < 64; i++) s += hsm[m * 65 + i] * hsm[m2 * 65 + i];
        float v = s * (1.0f / 63.0f);
        if (m == m2) v += rr;
        P[((size_t)b * 64 + m) * 64 + m2] = v;
        if (out_sig) out_sig[(size_t)b * 4096 + m * 64 + m2] = v;
    }
}

// in-place Cholesky of 64x64, pitch 65, lower triangle (256 threads)
__device__ void chol64(float* A, int tid) {
    for (int k = 0; k < 64; k++) {
        if (tid == 0) A[k * 65 + k] = sqrtf(A[k * 65 + k]);
        __syncthreads();
        float lkk = A[k * 65 + k];
        for (int r = k + 1 + tid; r < 64; r += 256) A[r * 65 + k] /= lkk;
        __syncthreads();
        int rem = 63 - k;
        for (int idx = tid; idx < rem * rem; idx += 256) {
            int r = k + 1 + idx / rem, c2 = k + 1 + idx % rem;
            if (c2 <= r) A[r * 65 + c2] -= A[r * 65 + k] * A[c2 * 65 + k];
        }
        __syncthreads();
    }
}

// ---------- sol = P_f^{-1} (y - hxi_f) ----------
__global__ void __launch_bounds__(256) ek_cholsolve(const float* __restrict__ y) {
    const int b = blockIdx.x, tid = threadIdx.x;
    __shared__ float A[64 * 65];
    __shared__ float X[64 * 64];
    for (int idx = tid; idx < 4096; idx += 256) {
        int m = idx >> 6, mm = idx & 63;
        A[m * 65 + mm] = g_P_f[(size_t)b * 4096 + idx];
        X[idx] = y[b * 64 + m] - g_hxi[(size_t)b * 4096 + idx];
    }
    __syncthreads();
    chol64(A, tid);
    for (int k = 0; k < 64; k++) {
        if (tid < 64) X[k * 64 + tid] /= A[k * 65 + k];
        __syncthreads();
        int rem = 63 - k;
        for (int idx = tid; idx < rem * 64; idx += 256) {
            int r = k + 1 + (idx >> 6), i = idx & 63;
            X[r * 64 + i] -= A[r * 65 + k] * X[k * 64 + i];
        }
        __syncthreads();
    }
    for (int k = 63; k >= 0; k--) {
        if (tid < 64) X[k * 64 + tid] /= A[k * 65 + k];
        __syncthreads();
        for (int idx = tid; idx < k * 64; idx += 256) {
            int r = idx >> 6, i = idx & 63;
            X[r * 64 + i] -= A[k * 65 + r] * X[k * 64 + i];
        }
        __syncthreads();
    }
    for (int idx = tid; idx < 4096; idx += 256) g_sol[(size_t)b * 4096 + idx] = X[idx];
}

// ---------- state_a = state_f + A @ (HA^T sol)/63 ----------
__global__ void __launch_bounds__(256) ek_update(float* __restrict__ out_state) {
    const int b = blockIdx.x, tid = threadIdx.x;
    __shared__ float HAs[4096];
    __shared__ float sols[4096];
    for (int idx = tid; idx < 4096; idx += 256) {
        HAs[idx]  = g_HA[(size_t)b * 4096 + idx];
        sols[idx] = g_sol[(size_t)b * 4096 + idx];
    }
    __syncthreads();
    const int i = tid & 63, jg = tid >> 6;
    float m1r[16];
    for (int ji = 0; ji < 16; ji++) {
        int j = jg * 16 + ji;
        float s = 0.f;
        for (int m = 0; m < 64; m++) s += HAs[m * 64 + j] * sols[m * 64 + i];
        m1r[ji] = s * (1.0f / 63.0f);
    }
    __syncthreads();
    for (int ji = 0; ji < 16; ji++) HAs[(jg * 16 + ji) * 64 + i] = m1r[ji];
    {
        float s = 0.f;
        const float* row = g_state_f + ((size_t)b * NHID + tid) * 64;
        for (int ii = 0; ii < 64; ii++) s += row[ii];
        sols[tid] = s * (1.0f / 64.0f);
    }
    __syncthreads();
    for (int n = jg; n < NHID; n += 4) {
        float mn = sols[n];
        const float* row = g_state_f + ((size_t)b * NHID + n) * 64;
        float acc = 0.f;
        #pragma unroll 8
        for (int j = 0; j < 64; j++) acc += (row[j] - mn) * HAs[j * 64 + i];
        float v = row[i] + acc;
        g_state_a[((size_t)b * NHID + n) * 64 + i] = v;
        out_state[((size_t)b * NHID + n) * 64 + i] = v;
    }
}

// ---------- per-batch loglik / NIS on (hx_a, P_a) ----------
__global__ void __launch_bounds__(256) ek_loglik(const float* __restrict__ y) {
    const int b = blockIdx.x, tid = threadIdx.x;
    __shared__ float A[64 * 65];
    __shared__ float iv[64], v[64];
    for (int idx = tid; idx < 4096; idx += 256) {
        int m = idx >> 6, mm = idx & 63;
        A[m * 65 + mm] = g_P_a[(size_t)b * 4096 + idx] + (m == mm ? 1e-6f : 0.f);
    }
    if (tid < 64) {
        float d = y[b * 64 + tid] - g_hx_a[b * 64 + tid];
        iv[tid] = d; v[tid] = d;
    }
    __syncthreads();
    chol64(A, tid);
    for (int k = 0; k < 64; k++) {
        if (tid == 0) v[k] /= A[k * 65 + k];
        __syncthreads();
        if (tid > k && tid < 64) v[tid] -= A[tid * 65 + k] * v[k];
        __syncthreads();
    }
    for (int k = 63; k >= 0; k--) {
        if (tid == 0) v[k] /= A[k * 65 + k];
        __syncthreads();
        if (tid < k) v[tid] -= A[k * 65 + tid] * v[k];
        __syncthreads();
    }
    if (tid == 0) {
        float quad = 0.f, ld = 0.f;
        for (int m = 0; m < 64; m++) { quad += iv[m] * v[m]; ld += __logf(A[m * 65 + m]); }
        g_part[b * 2] = quad;
        g_part[b * 2 + 1] = 2.f * ld;
    }
}

__global__ void ek_reduce(float* __restrict__ out) {
    int t = threadIdx.x;  // 32 threads
    float q = g_part[t * 2], ld = g_part[t * 2 + 1];
    float l = -0.5f * ld - 0.5f * q;
    #pragma unroll
    for (int s = 16; s; s >>= 1) {
        l += __shfl_xor_sync(0xffffffffu, l, s);
        q += __shfl_xor_sync(0xffffffffu, q, s);
    }
    if (t == 0) { out[0] = l; out[1] = q * (1.0f / 32.0f); }
}

extern "C" void kernel_launch(void* const* d_in, const int* in_sizes, int n_in,
                              void* d_out, int out_size) {
    const float* x    = (const float*)d_in[0];
    const float* y    = (const float*)d_in[1];
    const float* st0  = (const float*)d_in[2];
    const float* Wih  = (const float*)d_in[3];
    const float* Whh  = (const float*)d_in[4];
    const float* bias = (const float*)d_in[5];
    const float* Wh   = (const float*)d_in[6];
    const float* bh   = (const float*)d_in[7];
    const float* q    = (const float*)d_in[8];
    const float* e    = (const float*)d_in[9];
    const float* r    = (const float*)d_in[10];
    const float* eph  = (const float*)d_in[11];
    const float* epc  = (const float*)d_in[12];

    float* out       = (float*)d_out;
    float* out_mu    = out;                   // [32*64]
    float* out_sig   = out + 2048;            // [32*64*64]
    float* out_state = out + 2048 + 131072;   // [32*256*64]
    float* out_l     = out + 2048 + 131072 + 524288;  // l, then nis

    const int SMEM_LSTM = ND * TILEB + 16384 + 256;
    static int smem_set = 0;
    if (!smem_set) {
        cudaFuncSetAttribute(ek_lstm, cudaFuncAttributeMaxDynamicSharedMemorySize,
                             SMEM_LSTM);
        smem_set = 1;
    }

    ek_wprep<<<256, 256>>>(Whh);
    ek_gx<<<dim3(16, 32), 256>>>(x, Wih, bias);
    ek_lstm<<<128, NTHR, SMEM_LSTM>>>(st0, eph, epc, q, e);

    float* hxi; cudaGetSymbolAddress((void**)&hxi, g_hxi);
    float* sf;  cudaGetSymbolAddress((void**)&sf, g_state_f);
    float* sa;  cudaGetSymbolAddress((void**)&sa, g_state_a);
    float* hxf; cudaGetSymbolAddress((void**)&hxf, g_hx_f);
    float* hxa; cudaGetSymbolAddress((void**)&hxa, g_hx_a);
    float* pf;  cudaGetSymbolAddress((void**)&pf, g_P_f);
    float* pa;  cudaGetSymbolAddress((void**)&pa, g_P_a);

    // forecast stats -> EnKF solve -> analysis state
    ek_obs<<<32, 256>>>(Wh, bh, sf, hxi);
    ek_stats<<<32, 256>>>(r, hxi, hxf, pf, 1, nullptr, nullptr);
    ek_cholsolve<<<32, 256>>>(y);
    ek_update<<<32, 256>>>(out_state);
    // analysis stats (train branch: mu/sig from filtered ensemble)
    ek_obs<<<32, 256>>>(Wh, bh, sa, hxi);
    ek_stats<<<32, 256>>>(r, hxi, hxa, pa, 0, out_mu, out_sig);
    ek_loglik<<<32, 256>>>(y);
    ek_reduce<<<1, 32>>>(out_l);
    (void)in_sizes; (void)n_in; (void)out_size;
}

// round 7
// speedup vs baseline: 2.8870x; 2.8870x over previous
#include <cuda_runtime.h>
#include <math.h>

#define SEQN 64
#define BSN  32
#define NHID 256
#define G4   1024

#define TK        16                    // k-rows per W tile
#define ND        3                     // ring depth
#define TILEB     (TK * G4 * 4)         // 65536 bytes per tile
#define NT_STEP   (NHID / TK)           // 16 tiles per step
#define NT_TOT    (SEQN * NT_STEP)      // 1024 tiles total
#define NTHR      288                   // 8 compute warps + 1 producer warp

__device__ float  g_Gx[BSN * SEQN * G4];
__device__ float4 g_Wt[256 * 256];
__device__ float  g_state_f[BSN * NHID * 64];
__device__ float  g_state_a[BSN * NHID * 64];
__device__ float  g_hxi[BSN * 64 * 64];
__device__ float  g_hx_f[BSN * 64];
__device__ float  g_hx_a[BSN * 64];
__device__ float  g_P_f[BSN * 64 * 64];
__device__ float  g_P_a[BSN * 64 * 64];
__device__ float  g_HA[BSN * 64 * 64];
__device__ float  g_sol[BSN * 64 * 64];
__device__ float  g_part[BSN * 2];

typedef unsigned long long ull;

__device__ __forceinline__ ull pk2(float a, float b) {
    ull r;
    asm("mov.b64 %0, {%1, %2};" : "=l"(r) : "f"(a), "f"(b));
    return r;
}
__device__ __forceinline__ float2 upk2(ull v) {
    float2 r;
    asm("mov.b64 {%0, %1}, %2;" : "=f"(r.x), "=f"(r.y) : "l"(v));
    return r;
}
__device__ __forceinline__ void fma2(ull& acc, ull a, ull b) {
    asm("fma.rn.f32x2 %0, %1, %2, %0;" : "+l"(acc) : "l"(a), "l"(b));
}
__device__ __forceinline__ float sigf(float x) { return 1.0f / (1.0f + __expf(-x)); }

__device__ __forceinline__ unsigned smem_u32(const void* p) {
    unsigned a;
    asm("{ .reg .u64 t; cvta.to.shared.u64 t, %1; cvt.u32.u64 %0, t; }"
        : "=r"(a) : "l"(p));
    return a;
}
__device__ __forceinline__ void mbar_init(unsigned mbar, unsigned cnt) {
    asm volatile("mbarrier.init.shared.b64 [%0], %1;" :: "r"(mbar), "r"(cnt) : "memory");
}
__device__ __forceinline__ void mbar_expect_tx(unsigned mbar, unsigned bytes) {
    asm volatile("mbarrier.arrive.expect_tx.shared.b64 _, [%0], %1;"
                 :: "r"(mbar), "r"(bytes) : "memory");
}
__device__ __forceinline__ void mbar_arrive_local(unsigned mbar) {
    asm volatile("mbarrier.arrive.shared.b64 _, [%0];" :: "r"(mbar) : "memory");
}
__device__ __forceinline__ void mbar_wait(unsigned mbar, unsigned phase) {
    asm volatile(
        "{\n\t"
        ".reg .pred P;\n\t"
        "LW%=:\n\t"
        "mbarrier.try_wait.parity.acquire.cta.shared::cta.b64 P, [%0], %1, 0x989680;\n\t"
        "@P bra LD%=;\n\t"
        "bra LW%=;\n\t"
        "LD%=:\n\t"
        "}"
        :: "r"(mbar), "r"(phase) : "memory");
}
__device__ __forceinline__ void bulk_g2s(unsigned dst, const void* src,
                                         unsigned bytes, unsigned mbar) {
    asm volatile(
        "cp.async.bulk.shared::cta.global.mbarrier::complete_tx::bytes [%0], [%1], %2, [%3];"
        :: "r"(dst), "l"(src), "r"(bytes), "r"(mbar) : "memory");
}
#define CBAR() asm volatile("bar.sync 1, 256;" ::: "memory")   // compute warps only

// ---------- W_hh -> gate-interleaved float4 layout ----------
__global__ void ek_wprep(const float* __restrict__ W) {
    int k = blockIdx.x, j = threadIdx.x;
    g_Wt[k * 256 + j] = make_float4(W[k * G4 + j], W[k * G4 + 256 + j],
                                    W[k * G4 + 512 + j], W[k * G4 + 768 + j]);
}

// ---------- Gx[b*64+t][1024] = x[b][t][:] @ W_ih + b ----------
__global__ void __launch_bounds__(256) ek_gx(const float* __restrict__ x,
                                             const float* __restrict__ Wih,
                                             const float* __restrict__ bias) {
    __shared__ float As[32][65];
    __shared__ float Bs[32][64];
    const int tid = threadIdx.x;
    const int row0 = blockIdx.y * 64, col0 = blockIdx.x * 64;
    const int ty = tid >> 4, tx = tid & 15;
    float acc[4][4] = {};
    for (int kb = 0; kb < 256; kb += 32) {
        #pragma unroll
        for (int l = 0; l < 8; l++) {
            int e = l * 256 + tid, r = e >> 5, k = e & 31;
            As[k][r] = x[(size_t)(row0 + r) * 256 + kb + k];
        }
        #pragma unroll
        for (int l = 0; l < 8; l++) {
            int e = l * 256 + tid, k = e >> 6, c = e & 63;
            Bs[k][c] = Wih[(size_t)(kb + k) * G4 + col0 + c];
        }
        __syncthreads();
        #pragma unroll
        for (int k = 0; k < 32; k++) {
            float av[4], bv[4];
            #pragma unroll
            for (int i = 0; i < 4; i++) av[i] = As[k][ty * 4 + i];
            #pragma unroll
            for (int j = 0; j < 4; j++) bv[j] = Bs[k][tx * 4 + j];
            #pragma unroll
            for (int i = 0; i < 4; i++)
                #pragma unroll
                for (int j = 0; j < 4; j++) acc[i][j] += av[i] * bv[j];
        }
        __syncthreads();
    }
    #pragma unroll
    for (int i = 0; i < 4; i++)
        #pragma unroll
        for (int j = 0; j < 4; j++)
            g_Gx[(size_t)(row0 + ty * 4 + i) * G4 + col0 + tx * 4 + j] =
                acc[i][j] + bias[col0 + tx * 4 + j];
}

// ---------- LSTM recurrence: 128 CTAs = (batch, member-group of 8) ----------
// Per-CTA bulk-async W ring (no clusters). Warp specialization:
// warps 0-7 compute (threads 0-255), warp 8 produces. Compute warps never
// block on the refill protocol: per tile they wait full[s], compute, and do
// one elected per-warp arrive on cons[s]; the producer warp waits cons[s]
// (count=8) and refills. No per-tile __syncthreads.
__global__ void __launch_bounds__(NTHR, 1)
ek_lstm(const float* __restrict__ st0,
        const float* __restrict__ eps_h,
        const float* __restrict__ eps_c,
        const float* __restrict__ qp,
        const float* __restrict__ ep) {
    extern __shared__ char smd[];
    float4*     ws  = (float4*)smd;                           // ND * TK*256 float4
    ulonglong2* hsd = (ulonglong2*)(smd + ND * TILEB);        // [2][256][2]
    ull*        mbf = (ull*)(smd + ND * TILEB + 16384);       // full[ND]
    ull*        mbc = (ull*)(smd + ND * TILEB + 16384 + 64);  // cons[ND]

    const int jt = threadIdx.x;
    const int b  = blockIdx.x >> 2;
    const int m0 = (blockIdx.x & 3) * 8;
    const unsigned fb0 = smem_u32(mbf);
    const unsigned cb0 = smem_u32(mbc);
    const unsigned ws0 = smem_u32(ws);

    if (jt == 0) {
        #pragma unroll
        for (int d = 0; d < ND; d++) {
            mbar_init(fb0 + d * 8, 1);
            mbar_init(cb0 + d * 8, 8);     // 8 compute warps
        }
    }
    __syncthreads();

    if (jt >= 256) {
        // ---------------- producer warp ----------------
        if (jt == 256) {
            #pragma unroll
            for (int d = 0; d < ND; d++) {
                mbar_expect_tx(fb0 + d * 8, TILEB);
                bulk_g2s(ws0 + d * TILEB, (const char*)g_Wt + (size_t)d * TILEB,
                         TILEB, fb0 + d * 8);
            }
            for (unsigned g = 0; g + ND < NT_TOT; g++) {
                const unsigned s  = g % ND;
                const unsigned ph = (g / ND) & 1;
                mbar_wait(cb0 + s * 8, ph);          // all 8 warps consumed gen g
                unsigned src_tile = (g + ND) % NT_STEP;
                mbar_expect_tx(fb0 + s * 8, TILEB);
                bulk_g2s(ws0 + s * TILEB,
                         (const char*)g_Wt + (size_t)src_tile * TILEB,
                         TILEB, fb0 + s * 8);
            }
        }
    } else {
        // ---------------- compute warps ----------------
        const bool lead = ((jt & 31) == 0);
        float c[8];
        {
            const float* srow = st0 + ((size_t)b * NHID + jt) * 64;
            float h0[8];
            #pragma unroll
            for (int i = 0; i < 8; i++) { h0[i] = srow[m0 + i]; c[i] = srow[32 + m0 + i]; }
            #pragma unroll
            for (int p = 0; p < 2; p++) {
                ulonglong2 v;
                v.x = pk2(h0[4 * p], h0[4 * p + 1]);
                v.y = pk2(h0[4 * p + 2], h0[4 * p + 3]);
                hsd[(0 * 256 + jt) * 2 + p] = v;
            }
        }
        CBAR();

        unsigned g = 0;
        for (int t = 0; t < SEQN; t++) {
            const int cb = t & 1, nb = cb ^ 1;
            const float* gx = g_Gx + ((size_t)b * SEQN + t) * G4 + jt;
            ull acc[4][4];
            #pragma unroll
            for (int gg = 0; gg < 4; gg++) {
                float gv = gx[gg * 256];
                ull gp = pk2(gv, gv);
                #pragma unroll
                for (int p = 0; p < 4; p++) acc[p][gg] = gp;
            }
            for (int tile = 0; tile < NT_STEP; tile++, g++) {
                const unsigned s  = g % ND;
                const unsigned ph = (g / ND) & 1;
                mbar_wait(fb0 + s * 8, ph);
                const float4* wt = ws + (size_t)s * (TK * 256) + jt;
                const ulonglong2* hp = hsd + ((size_t)cb * 256 + tile * TK) * 2;
                #pragma unroll
                for (int kk = 0; kk < TK; kk++) {
                    float4 w = wt[kk * 256];
                    ulonglong2 h01 = hp[kk * 2 + 0];
                    ulonglong2 h23 = hp[kk * 2 + 1];
                    ull wp0 = pk2(w.x, w.x), wp1 = pk2(w.y, w.y);
                    ull wp2 = pk2(w.z, w.z), wp3 = pk2(w.w, w.w);
                    fma2(acc[0][0], h01.x, wp0); fma2(acc[0][1], h01.x, wp1);
                    fma2(acc[0][2], h01.x, wp2); fma2(acc[0][3], h01.x, wp3);
                    fma2(acc[1][0], h01.y, wp0); fma2(acc[1][1], h01.y, wp1);
                    fma2(acc[1][2], h01.y, wp2); fma2(acc[1][3], h01.y, wp3);
                    fma2(acc[2][0], h23.x, wp0); fma2(acc[2][1], h23.x, wp1);
                    fma2(acc[2][2], h23.x, wp2); fma2(acc[2][3], h23.x, wp3);
                    fma2(acc[3][0], h23.y, wp0); fma2(acc[3][1], h23.y, wp1);
                    fma2(acc[3][2], h23.y, wp2); fma2(acc[3][3], h23.y, wp3);
                }
                if (lead) mbar_arrive_local(cb0 + s * 8);   // this warp done with gen g
            }
            {
                ulonglong2 v0, v1;
                {
                    float2 gi = upk2(acc[0][0]), gf = upk2(acc[0][1]);
                    float2 gg2 = upk2(acc[0][2]), go = upk2(acc[0][3]);
                    float c0 = sigf(gf.x) * c[0] + sigf(gi.x) * tanhf(gg2.x);
                    float c1 = sigf(gf.y) * c[1] + sigf(gi.y) * tanhf(gg2.y);
                    c[0] = c0; c[1] = c1;
                    v0.x = pk2(sigf(go.x) * tanhf(c0), sigf(go.y) * tanhf(c1));
                }
                {
                    float2 gi = upk2(acc[1][0]), gf = upk2(acc[1][1]);
                    float2 gg2 = upk2(acc[1][2]), go = upk2(acc[1][3]);
                    float c0 = sigf(gf.x) * c[2] + sigf(gi.x) * tanhf(gg2.x);
                    float c1 = sigf(gf.y) * c[3] + sigf(gi.y) * tanhf(gg2.y);
                    c[2] = c0; c[3] = c1;
                    v0.y = pk2(sigf(go.x) * tanhf(c0), sigf(go.y) * tanhf(c1));
                }
                {
                    float2 gi = upk2(acc[2][0]), gf = upk2(acc[2][1]);
                    float2 gg2 = upk2(acc[2][2]), go = upk2(acc[2][3]);
                    float c0 = sigf(gf.x) * c[4] + sigf(gi.x) * tanhf(gg2.x);
                    float c1 = sigf(gf.y) * c[5] + sigf(gi.y) * tanhf(gg2.y);
                    c[4] = c0; c[5] = c1;
                    v1.x = pk2(sigf(go.x) * tanhf(c0), sigf(go.y) * tanhf(c1));
                }
                {
                    float2 gi = upk2(acc[3][0]), gf = upk2(acc[3][1]);
                    float2 gg2 = upk2(acc[3][2]), go = upk2(acc[3][3]);
                    float c0 = sigf(gf.x) * c[6] + sigf(gi.x) * tanhf(gg2.x);
                    float c1 = sigf(gf.y) * c[7] + sigf(gi.y) * tanhf(gg2.y);
                    c[6] = c0; c[7] = c1;
                    v1.y = pk2(sigf(go.x) * tanhf(c0), sigf(go.y) * tanhf(c1));
                }
                hsd[(nb * 256 + jt) * 2 + 0] = v0;
                hsd[(nb * 256 + jt) * 2 + 1] = v1;
            }
            CBAR();   // new h visible before next step (compute warps only)
        }

        const float nq = fabsf(qp[0]), ne = fabsf(ep[0]);
        float* orow = g_state_f + ((size_t)b * NHID + jt) * 64;
        ulonglong2 f0 = hsd[(0 * 256 + jt) * 2 + 0];
        ulonglong2 f1 = hsd[(0 * 256 + jt) * 2 + 1];
        float2 hf[4] = { upk2(f0.x), upk2(f0.y), upk2(f1.x), upk2(f1.y) };
        #pragma unroll
        for (int p = 0; p < 4; p++) {
            int ma = m0 + 2 * p, mb2 = ma + 1;
            orow[ma]  = hf[p].x + nq * eps_h[((size_t)ma * BSN + b) * NHID + jt];
            orow[mb2] = hf[p].y + nq * eps_h[((size_t)mb2 * BSN + b) * NHID + jt];
            orow[32 + ma]  = c[2 * p]     + ne * eps_c[((size_t)ma * BSN + b) * NHID + jt];
            orow[32 + mb2] = c[2 * p + 1] + ne * eps_c[((size_t)mb2 * BSN + b) * NHID + jt];
        }
    }
}

// ---------- hxi[b][m][i] = Wh[m][:] @ state[b][:][i] + bh[m] ----------
__global__ void __launch_bounds__(256) ek_obs(const float* __restrict__ Wh,
                                              const float* __restrict__ bh,
                                              const float* __restrict__ state,
                                              float* __restrict__ hxi) {
    const int b = blockIdx.x, tid = threadIdx.x;
    __shared__ float whs[64 * 64];
    __shared__ float ss[64 * 64];
    const int i = tid & 63, mg = tid >> 6;
    float acc[16] = {};
    for (int nt = 0; nt < NHID; nt += 64) {
        for (int idx = tid; idx < 4096; idx += 256) {
            whs[idx] = Wh[(size_t)(idx >> 6) * NHID + nt + (idx & 63)];
            ss[idx]  = state[(size_t)b * (NHID * 64) + (size_t)(nt + (idx >> 6)) * 64 + (idx & 63)];
        }
        __syncthreads();
        #pragma unroll 4
        for (int n = 0; n < 64; n++) {
            float sv = ss[n * 64 + i];
            #pragma unroll
            for (int mi = 0; mi < 16; mi++)
                acc[mi] += whs[(mg * 16 + mi) * 64 + n] * sv;
        }
        __syncthreads();
    }
    #pragma unroll
    for (int mi = 0; mi < 16; mi++) {
        int m = mg * 16 + mi;
        hxi[((size_t)b * 64 + m) * 64 + i] = acc[mi] + bh[m];
    }
}

// ---------- mean / center / P = cov/63 + r^2 I ----------
__global__ void __launch_bounds__(256) ek_stats(const float* __restrict__ rp,
                                                const float* __restrict__ hxi,
                                                float* __restrict__ hx,
                                                float* __restrict__ P,
                                                int save_ha,
                                                float* __restrict__ out_mu,
                                                float* __restrict__ out_sig) {
    const int b = blockIdx.x, tid = threadIdx.x;
    __shared__ float hsm[64 * 65];
    __shared__ float mean_s[64];
    for (int idx = tid; idx < 4096; idx += 256) {
        int m = idx >> 6, i = idx & 63;
        hsm[m * 65 + i] = hxi[(size_t)b * 4096 + idx];
    }
    __syncthreads();
    if (tid < 64) {
        float s = 0.f;
        for (int i = 0; i < 64; i++) s += hsm[tid * 65 + i];
        s *= (1.0f / 64.0f);
        mean_s[tid] = s;
        hx[b * 64 + tid] = s;
        if (out_mu) out_mu[b * 64 + tid] = s;
    }
    __syncthreads();
    for (int idx = tid; idx < 4096; idx += 256) {
        int m = idx >> 6, i = idx & 63;
        float v = hsm[m * 65 + i] - mean_s[m];
        hsm[m * 65 + i] = v;
        if (save_ha) g_HA[(size_t)b * 4096 + idx] = v;
    }
    __syncthreads();
    const float rr = rp[0] * rp[0];
    const int m2 = tid & 63, mg = tid >> 6;
    for (int mi = 0; mi < 16; mi++) {
        int m = mg * 16 + mi;
        float s = 0.f;
        for (int i = 0; i < 64; i++) s += hsm[m * 65 + i] * hsm[m2 * 65 + i];
        float v = s * (1.0f / 63.0f);
        if (m == m2) v += rr;
        P[((size_t)b * 64 + m) * 64 + m2] = v;
        if (out_sig) out_sig[(size_t)b * 4096 + m * 64 + m2] = v;
    }
}

// in-place Cholesky of 64x64, pitch 65, lower triangle (256 threads)
__device__ void chol64(float* A, int tid) {
    for (int k = 0; k < 64; k++) {
        if (tid == 0) A[k * 65 + k] = sqrtf(A[k * 65 + k]);
        __syncthreads();
        float lkk = A[k * 65 + k];
        for (int r = k + 1 + tid; r < 64; r += 256) A[r * 65 + k] /= lkk;
        __syncthreads();
        int rem = 63 - k;
        for (int idx = tid; idx < rem * rem; idx += 256) {
            int r = k + 1 + idx / rem, c2 = k + 1 + idx % rem;
            if (c2 <= r) A[r * 65 + c2] -= A[r * 65 + k] * A[c2 * 65 + k];
        }
        __syncthreads();
    }
}

// ---------- sol = P_f^{-1} (y - hxi_f) ----------
__global__ void __launch_bounds__(256) ek_cholsolve(const float* __restrict__ y) {
    const int b = blockIdx.x, tid = threadIdx.x;
    __shared__ float A[64 * 65];
    __shared__ float X[64 * 64];
    for (int idx = tid; idx < 4096; idx += 256) {
        int m = idx >> 6, mm = idx & 63;
        A[m * 65 + mm] = g_P_f[(size_t)b * 4096 + idx];
        X[idx] = y[b * 64 + m] - g_hxi[(size_t)b * 4096 + idx];
    }
    __syncthreads();
    chol64(A, tid);
    for (int k = 0; k < 64; k++) {
        if (tid < 64) X[k * 64 + tid] /= A[k * 65 + k];
        __syncthreads();
        int rem = 63 - k;
        for (int idx = tid; idx < rem * 64; idx += 256) {
            int r = k + 1 + (idx >> 6), i = idx & 63;
            X[r * 64 + i] -= A[r * 65 + k] * X[k * 64 + i];
        }
        __syncthreads();
    }
    for (int k = 63; k >= 0; k--) {
        if (tid < 64) X[k * 64 + tid] /= A[k * 65 + k];
        __syncthreads();
        for (int idx = tid; idx < k * 64; idx += 256) {
            int r = idx >> 6, i = idx & 63;
            X[r * 64 + i] -= A[k * 65 + r] * X[k * 64 + i];
        }
        __syncthreads();
    }
    for (int idx = tid; idx < 4096; idx += 256) g_sol[(size_t)b * 4096 + idx] = X[idx];
}

// ---------- state_a = state_f + A @ (HA^T sol)/63 ----------
__global__ void __launch_bounds__(256) ek_update(float* __restrict__ out_state) {
    const int b = blockIdx.x, tid = threadIdx.x;
    __shared__ float HAs[4096];
    __shared__ float sols[4096];
    for (int idx = tid; idx < 4096; idx += 256) {
        HAs[idx]  = g_HA[(size_t)b * 4096 + idx];
        sols[idx] = g_sol[(size_t)b * 4096 + idx];
    }
    __syncthreads();
    const int i = tid & 63, jg = tid >> 6;
    float m1r[16];
    for (int ji = 0; ji < 16; ji++) {
        int j = jg * 16 + ji;
        float s = 0.f;
        for (int m = 0; m < 64; m++) s += HAs[m * 64 + j] * sols[m * 64 + i];
        m1r[ji] = s * (1.0f / 63.0f);
    }
    __syncthreads();
    for (int ji = 0; ji < 16; ji++) HAs[(jg * 16 + ji) * 64 + i] = m1r[ji];
    {
        float s = 0.f;
        const float* row = g_state_f + ((size_t)b * NHID + tid) * 64;
        for (int ii = 0; ii < 64; ii++) s += row[ii];
        sols[tid] = s * (1.0f / 64.0f);
    }
    __syncthreads();
    for (int n = jg; n < NHID; n += 4) {
        float mn = sols[n];
        const float* row = g_state_f + ((size_t)b * NHID + n) * 64;
        float acc = 0.f;
        #pragma unroll 8
        for (int j = 0; j < 64; j++) acc += (row[j] - mn) * HAs[j * 64 + i];
        float v = row[i] + acc;
        g_state_a[((size_t)b * NHID + n) * 64 + i] = v;
        out_state[((size_t)b * NHID + n) * 64 + i] = v;
    }
}

// ---------- per-batch loglik / NIS on (hx_a, P_a) ----------
__global__ void __launch_bounds__(256) ek_loglik(const float* __restrict__ y) {
    const int b = blockIdx.x, tid = threadIdx.x;
    __shared__ float A[64 * 65];
    __shared__ float iv[64], v[64];
    for (int idx = tid; idx < 4096; idx += 256) {
        int m = idx >> 6, mm = idx & 63;
        A[m * 65 + mm] = g_P_a[(size_t)b * 4096 + idx] + (m == mm ? 1e-6f : 0.f);
    }
    if (tid < 64) {
        float d = y[b * 64 + tid] - g_hx_a[b * 64 + tid];
        iv[tid] = d; v[tid] = d;
    }
    __syncthreads();
    chol64(A, tid);
    for (int k = 0; k < 64; k++) {
        if (tid == 0) v[k] /= A[k * 65 + k];
        __syncthreads();
        if (tid > k && tid < 64) v[tid] -= A[tid * 65 + k] * v[k];
        __syncthreads();
    }
    for (int k = 63; k >= 0; k--) {
        if (tid == 0) v[k] /= A[k * 65 + k];
        __syncthreads();
        if (tid < k) v[tid] -= A[k * 65 + tid] * v[k];
        __syncthreads();
    }
    if (tid == 0) {
        float quad = 0.f, ld = 0.f;
        for (int m = 0; m < 64; m++) { quad += iv[m] * v[m]; ld += __logf(A[m * 65 + m]); }
        g_part[b * 2] = quad;
        g_part[b * 2 + 1] = 2.f * ld;
    }
}

__global__ void ek_reduce(float* __restrict__ out) {
    int t = threadIdx.x;  // 32 threads
    float q = g_part[t * 2], ld = g_part[t * 2 + 1];
    float l = -0.5f * ld - 0.5f * q;
    #pragma unroll
    for (int s = 16; s; s >>= 1) {
        l += __shfl_xor_sync(0xffffffffu, l, s);
        q += __shfl_xor_sync(0xffffffffu, q, s);
    }
    if (t == 0) { out[0] = l; out[1] = q * (1.0f / 32.0f); }
}

extern "C" void kernel_launch(void* const* d_in, const int* in_sizes, int n_in,
                              void* d_out, int out_size) {
    const float* x    = (const float*)d_in[0];
    const float* y    = (const float*)d_in[1];
    const float* st0  = (const float*)d_in[2];
    const float* Wih  = (const float*)d_in[3];
    const float* Whh  = (const float*)d_in[4];
    const float* bias = (const float*)d_in[5];
    const float* Wh   = (const float*)d_in[6];
    const float* bh   = (const float*)d_in[7];
    const float* q    = (const float*)d_in[8];
    const float* e    = (const float*)d_in[9];
    const float* r    = (const float*)d_in[10];
    const float* eph  = (const float*)d_in[11];
    const float* epc  = (const float*)d_in[12];

    float* out       = (float*)d_out;
    float* out_mu    = out;                   // [32*64]
    float* out_sig   = out + 2048;            // [32*64*64]
    float* out_state = out + 2048 + 131072;   // [32*256*64]
    float* out_l     = out + 2048 + 131072 + 524288;  // l, then nis

    const int SMEM_LSTM = ND * TILEB + 16384 + 256;
    static int smem_set = 0;
    if (!smem_set) {
        cudaFuncSetAttribute(ek_lstm, cudaFuncAttributeMaxDynamicSharedMemorySize,
                             SMEM_LSTM);
        smem_set = 1;
    }

    ek_wprep<<<256, 256>>>(Whh);
    ek_gx<<<dim3(16, 32), 256>>>(x, Wih, bias);
    ek_lstm<<<128, NTHR, SMEM_LSTM>>>(st0, eph, epc, q, e);

    float* hxi; cudaGetSymbolAddress((void**)&hxi, g_hxi);
    float* sf;  cudaGetSymbolAddress((void**)&sf, g_state_f);
    float* sa;  cudaGetSymbolAddress((void**)&sa, g_state_a);
    float* hxf; cudaGetSymbolAddress((void**)&hxf, g_hx_f);
    float* hxa; cudaGetSymbolAddress((void**)&hxa, g_hx_a);
    float* pf;  cudaGetSymbolAddress((void**)&pf, g_P_f);
    float* pa;  cudaGetSymbolAddress((void**)&pa, g_P_a);

    // forecast stats -> EnKF solve -> analysis state
    ek_obs<<<32, 256>>>(Wh, bh, sf, hxi);
    ek_stats<<<32, 256>>>(r, hxi, hxf, pf, 1, nullptr, nullptr);
    ek_cholsolve<<<32, 256>>>(y);
    ek_update<<<32, 256>>>(out_state);
    // analysis stats (train branch: mu/sig from filtered ensemble)
    ek_obs<<<32, 256>>>(Wh, bh, sa, hxi);
    ek_stats<<<32, 256>>>(r, hxi, hxa, pa, 0, out_mu, out_sig);
    ek_loglik<<<32, 256>>>(y);
    ek_reduce<<<1, 32>>>(out_l);
    (void)in_sizes; (void)n_in; (void)out_size;
}